// round 10
// baseline (speedup 1.0000x reference)
#include <cuda_runtime.h>

// Shape (fixed by reference)
#define B_     16
#define T_     4096
#define D_     512
#define L_     32                 // t-steps per block tile
#define Q_     8                  // t-steps per rescan quarter
#define DG_    256                // d-lanes per block (wide: 1KB read / 2KB write rows)
#define NDG    (D_ / DG_)         // 2
#define C_     (T_ / L_)          // 128 chunks per chain
#define NCHAIN (B_ * NDG)         // 32 chains
#define NBLK   (NCHAIN * C_)      // 4096 blocks
#define THREADS 256

// Decoupled-lookback state. Flags/counters are restored to ZERO by the kernel
// itself before exit (self-cleaning): one launch per call, identical all-zero
// start state on every launch/replay.
__device__ float2 g_agg [(size_t)NBLK * DG_];   // local aggregates   (8 MB)
__device__ float2 g_incl[(size_t)NBLK * DG_];   // inclusive prefixes (8 MB)
__device__ int    g_flag[NBLK];                 // 0=none, 1=agg, 2=inclusive
__device__ int    g_done[NCHAIN];               // per-chain reader counters

// ---------------------------------------------------------------------------
// Warp-specialized decoupled-lookback scan, wide-DG variant.
//   bid = c*NCHAIN + chain.
//   h1 (tid 128..255): tile load (32KB, contiguous 1KB rows), 32-step scan of
//      2 adjacent d-lanes each (ILP=2); snapshots at t=8/16/24 written straight
//      into sqin[1..3]; aggregate published (float4).
//   h0 (tid 0..127): lookback with float4 hops (2 lanes/thread) -> carry in
//      sqin[0]; publishes inclusive in phase 2.
//   Cleanup accounting at the pre-store join. Phase 3: 4 quarters x 64 lanes
//      x 4 d-lanes, 2x STG.128 per step (2KB contiguous per row per block).
// ---------------------------------------------------------------------------
__global__ void __launch_bounds__(THREADS, 5) scan_kernel(
    const float* __restrict__ x,
    const float* __restrict__ Ar,
    const float* __restrict__ Ai,
    float2* __restrict__ out)
{
    __shared__ float  sx[L_ * DG_];      // 32 KB x tile, [t][d]
    __shared__ float2 sqin[4][DG_];      // [0]=carry; [1..3]=snapshots->entries (8 KB)
    __shared__ float2 sagg[DG_];         // block aggregate (h1 -> h0)  (2 KB)

    const int tid   = threadIdx.x;
    const int bid   = blockIdx.x;
    const int chain = bid & (NCHAIN - 1);
    const int c     = bid >> 5;                 // / NCHAIN
    const int dg    = chain & (NDG - 1);
    const int b     = chain >> 1;               // / NDG
    const int h     = tid >> 7;                 // 0: lookback, 1: scan

    if (h == 1) {
        // ===== h1: tile load + 2-lane 32-step scan + agg publish =============
        const int idx = tid - 128;              // 0..127
        const int d0  = 2 * idx;
        const float ar0 = Ar[dg * DG_ + d0],     ai0 = Ai[dg * DG_ + d0];
        const float ar1 = Ar[dg * DG_ + d0 + 1], ai1 = Ai[dg * DG_ + d0 + 1];

        const float* xb = x + ((size_t)b * T_ + (size_t)c * L_) * D_ + dg * DG_;
        {
            const int lane4 = idx & 63;         // float4 column (64 per row)
            const int rsub  = idx >> 6;         // 0..1
            float4* s4 = (float4*)sx;
            #pragma unroll
            for (int r = 0; r < L_ / 2; ++r) {
                const int row = r * 2 + rsub;
                s4[row * (DG_ / 4) + lane4] =
                    __ldcs((const float4*)(xb + (size_t)row * D_) + lane4);
            }
        }
        asm volatile("bar.sync 1, 128;" ::: "memory");   // tile ready (h1)

        const float2* sxd = (const float2*)sx + idx;     // (d0,d0+1) per row
        float r0 = 0.f, i0 = 0.f, r1 = 0.f, i1 = 0.f;
        #pragma unroll
        for (int t = 0; t < L_; ++t) {
            const float2 xv = sxd[t * (DG_ / 2)];
            const float n0r = fmaf(r0, ar0, fmaf(-i0, ai0, xv.x));
            const float n0i = fmaf(r0, ai0, i0 * ar0);
            const float n1r = fmaf(r1, ar1, fmaf(-i1, ai1, xv.y));
            const float n1i = fmaf(r1, ai1, i1 * ar1);
            r0 = n0r; i0 = n0i; r1 = n1r; i1 = n1i;
            if (t == Q_ - 1)     ((float4*)sqin[1])[idx] = make_float4(r0, i0, r1, i1);
            if (t == 2*Q_ - 1)   ((float4*)sqin[2])[idx] = make_float4(r0, i0, r1, i1);
            if (t == 3*Q_ - 1)   ((float4*)sqin[3])[idx] = make_float4(r0, i0, r1, i1);
        }
        const float4 aggv = make_float4(r0, i0, r1, i1);
        ((float4*)sagg)[idx] = aggv;

        if (c == 0) {
            ((float4*)(g_incl + (size_t)bid * DG_))[idx] = aggv;
        } else if (c < C_ - 1) {
            ((float4*)(g_agg + (size_t)bid * DG_))[idx] = aggv;
        }
        __threadfence();
        asm volatile("bar.sync 1, 128;" ::: "memory");
        if (tid == 128 && c < C_ - 1) atomicExch(&g_flag[bid], c == 0 ? 2 : 1);

        __syncthreads();   // join: carry (sqin[0]) valid

        // ---- phase 2: entries[q] = A^{8q}*carry + snapshot[q] ---------------
        // powers A^8, A^16, A^24 per lane
        float p8r0 = ar0, p8i0 = ai0, p8r1 = ar1, p8i1 = ai1;
        #pragma unroll
        for (int k = 0; k < 3; ++k) {
            float t0r = p8r0*p8r0 - p8i0*p8i0, t0i = 2.f*p8r0*p8i0;
            float t1r = p8r1*p8r1 - p8i1*p8i1, t1i = 2.f*p8r1*p8i1;
            p8r0 = t0r; p8i0 = t0i; p8r1 = t1r; p8i1 = t1i;
        }
        const float p16r0 = p8r0*p8r0 - p8i0*p8i0, p16i0 = 2.f*p8r0*p8i0;
        const float p16r1 = p8r1*p8r1 - p8i1*p8i1, p16i1 = 2.f*p8r1*p8i1;
        const float p24r0 = p16r0*p8r0 - p16i0*p8i0, p24i0 = p16r0*p8i0 + p16i0*p8r0;
        const float p24r1 = p16r1*p8r1 - p16i1*p8i1, p24i1 = p16r1*p8i1 + p16i1*p8r1;

        const float4 cv = ((float4*)sqin[0])[idx];       // carries (d0, d0+1)
        {
            float4 s = ((float4*)sqin[1])[idx];
            s.x = fmaf(p8r0, cv.x, fmaf(-p8i0, cv.y, s.x));
            s.y = fmaf(p8i0, cv.x, fmaf( p8r0, cv.y, s.y));
            s.z = fmaf(p8r1, cv.z, fmaf(-p8i1, cv.w, s.z));
            s.w = fmaf(p8i1, cv.z, fmaf( p8r1, cv.w, s.w));
            ((float4*)sqin[1])[idx] = s;
        }
        {
            float4 s = ((float4*)sqin[2])[idx];
            s.x = fmaf(p16r0, cv.x, fmaf(-p16i0, cv.y, s.x));
            s.y = fmaf(p16i0, cv.x, fmaf( p16r0, cv.y, s.y));
            s.z = fmaf(p16r1, cv.z, fmaf(-p16i1, cv.w, s.z));
            s.w = fmaf(p16i1, cv.z, fmaf( p16r1, cv.w, s.w));
            ((float4*)sqin[2])[idx] = s;
        }
        {
            float4 s = ((float4*)sqin[3])[idx];
            s.x = fmaf(p24r0, cv.x, fmaf(-p24i0, cv.y, s.x));
            s.y = fmaf(p24i0, cv.x, fmaf( p24r0, cv.y, s.y));
            s.z = fmaf(p24r1, cv.z, fmaf(-p24i1, cv.w, s.z));
            s.w = fmaf(p24i1, cv.z, fmaf( p24r1, cv.w, s.w));
            ((float4*)sqin[3])[idx] = s;
        }
    } else {
        // ===== h0: lookback (2 lanes/thread) concurrent with h1's scan =======
        const int idx = tid;                    // 0..127
        const int d0  = 2 * idx;
        const float ar0 = Ar[dg * DG_ + d0],     ai0 = Ai[dg * DG_ + d0];
        const float ar1 = Ar[dg * DG_ + d0 + 1], ai1 = Ai[dg * DG_ + d0 + 1];

        // A^32 per lane (5 squarings)
        float p0r = ar0, p0i = ai0, p1r = ar1, p1i = ai1;
        #pragma unroll
        for (int k = 0; k < 5; ++k) {
            float t0r = p0r*p0r - p0i*p0i, t0i = 2.f*p0r*p0i;
            float t1r = p1r*p1r - p1i*p1i, t1i = 2.f*p1r*p1i;
            p0r = t0r; p0i = t0i; p1r = t1r; p1i = t1i;
        }

        float c0r = 0.f, c0i = 0.f, c1r = 0.f, c1i = 0.f;
        if (c > 0) {
            float m0r = 1.f, m0i = 0.f, m1r = 1.f, m1i = 0.f;   // A^(32k)
            int j = bid - NCHAIN;
            while (true) {
                volatile int* f = &g_flag[j];
                int v = *f;
                while (v == 0) { __nanosleep(40); v = *f; }
                __threadfence();                 // acquire
                const float4 val = (v == 2)
                    ? __ldcg((const float4*)(g_incl + (size_t)j * DG_) + idx)
                    : __ldcg((const float4*)(g_agg  + (size_t)j * DG_) + idx);
                c0r = fmaf(m0r, val.x, fmaf(-m0i, val.y, c0r));
                c0i = fmaf(m0i, val.x, fmaf( m0r, val.y, c0i));
                c1r = fmaf(m1r, val.z, fmaf(-m1i, val.w, c1r));
                c1i = fmaf(m1i, val.z, fmaf( m1r, val.w, c1i));
                if (v == 2) break;               // prefix complete
                const float n0r = m0r*p0r - m0i*p0i, n0i = m0r*p0i + m0i*p0r;
                const float n1r = m1r*p1r - m1i*p1i, n1i = m1r*p1i + m1i*p1r;
                m0r = n0r; m0i = n0i; m1r = n1r; m1i = n1i;
                j -= NCHAIN;
            }
        }
        ((float4*)sqin[0])[idx] = make_float4(c0r, c0i, c1r, c1i);

        __syncthreads();   // join: sagg valid

        // ---- phase 2: publish inclusive = A^32*carry + agg ------------------
        if (c > 0 && c < C_ - 1) {
            const float4 ag = ((float4*)sagg)[idx];
            float4 inc;
            inc.x = fmaf(p0r, c0r, fmaf(-p0i, c0i, ag.x));
            inc.y = fmaf(p0i, c0r, fmaf( p0r, c0i, ag.y));
            inc.z = fmaf(p1r, c1r, fmaf(-p1i, c1i, ag.z));
            inc.w = fmaf(p1i, c1r, fmaf( p1r, c1i, ag.w));
            ((float4*)(g_incl + (size_t)bid * DG_))[idx] = inc;
            __threadfence();
            asm volatile("bar.sync 2, 128;" ::: "memory");
            if (tid == 0) atomicExch(&g_flag[bid], 2);
        }
    }

    __syncthreads();   // sqin[0..3] final; all flag reads/publishes complete.

    // ===== cleanup accounting (pre-store; overlaps with phase 3) =============
    if (c > 0 && tid == 0) {
        __threadfence();   // order my flag=2 publish before the counter bump
        if (atomicAdd(&g_done[chain], 1) == C_ - 2) {   // last reader of chain
            #pragma unroll 1
            for (int k = 0; k < C_ - 1; ++k)
                g_flag[k * NCHAIN + chain] = 0;
            g_done[chain] = 0;
            __threadfence();
        }
    }

    // ===== phase 3: 4 quarters x 64 lanes x 4 d-lanes, 2x float4 stores ======
    {
        const int q    = tid >> 6;               // 0..3
        const int lane = tid & 63;
        const int d0   = 4 * lane;
        const int dglb = dg * DG_ + d0;

        const float ar0 = Ar[dglb],     ai0 = Ai[dglb];
        const float ar1 = Ar[dglb + 1], ai1 = Ai[dglb + 1];
        const float ar2 = Ar[dglb + 2], ai2 = Ai[dglb + 2];
        const float ar3 = Ar[dglb + 3], ai3 = Ai[dglb + 3];

        const float4 e01 = ((const float4*)sqin[q])[2 * lane];
        const float4 e23 = ((const float4*)sqin[q])[2 * lane + 1];
        float r0 = e01.x, i0 = e01.y, r1 = e01.z, i1 = e01.w;
        float r2 = e23.x, i2 = e23.y, r3 = e23.z, i3 = e23.w;

        const float4* sx4 = (const float4*)sx + (size_t)q * Q_ * (DG_ / 4) + lane;
        float4* ob = (float4*)(out + ((size_t)b * T_ + (size_t)c * L_ + q * Q_) * D_ + dglb);

        #pragma unroll
        for (int t = 0; t < Q_; ++t) {
            const float4 xv = sx4[t * (DG_ / 4)];
            const float n0r = fmaf(r0, ar0, fmaf(-i0, ai0, xv.x));
            const float n0i = fmaf(r0, ai0, i0 * ar0);
            const float n1r = fmaf(r1, ar1, fmaf(-i1, ai1, xv.y));
            const float n1i = fmaf(r1, ai1, i1 * ar1);
            const float n2r = fmaf(r2, ar2, fmaf(-i2, ai2, xv.z));
            const float n2i = fmaf(r2, ai2, i2 * ar2);
            const float n3r = fmaf(r3, ar3, fmaf(-i3, ai3, xv.w));
            const float n3i = fmaf(r3, ai3, i3 * ar3);
            r0 = n0r; i0 = n0i; r1 = n1r; i1 = n1i;
            r2 = n2r; i2 = n2i; r3 = n3r; i3 = n3i;
            __stcs(&ob[(size_t)t * (D_ / 2)],     make_float4(n0r, n0i, n1r, n1i));
            __stcs(&ob[(size_t)t * (D_ / 2) + 1], make_float4(n2r, n2i, n3r, n3i));
        }
    }
}

// ---------------------------------------------------------------------------
// Inputs (metadata order): x [B*T*D] f32, A_real [D] f32, A_imag [D] f32.
// Output: [B, T, D, 2] f32.
// ---------------------------------------------------------------------------
extern "C" void kernel_launch(void* const* d_in, const int* in_sizes, int n_in,
                              void* d_out, int out_size)
{
    const float* x  = (const float*)d_in[0];
    const float* Ar = (const float*)d_in[1];
    const float* Ai = (const float*)d_in[2];
    float2* out = (float2*)d_out;

    scan_kernel<<<NBLK, THREADS>>>(x, Ar, Ai, out);
}

// round 11
// speedup vs baseline: 1.3458x; 1.3458x over previous
#include <cuda_runtime.h>

// Shape (fixed by reference)
#define B_     16
#define T_     4096
#define D_     512
#define L_     64                 // t-steps per block tile
#define Q_     16                 // t-steps per rescan quarter
#define DG_    128                // d-lanes per block
#define NDG    (D_ / DG_)         // 4
#define C_     (T_ / L_)          // 64 chunks per chain
#define NCHAIN (B_ * NDG)         // 64 chains
#define NBLK   (NCHAIN * C_)      // 4096 blocks
#define THREADS 256

// Decoupled-lookback state (static __device__ scratch; flags re-zeroed per
// launch by the tiny init kernel below).
__device__ float2 g_agg [(size_t)NBLK * DG_];   // local aggregates   (4 MB)
__device__ float2 g_incl[(size_t)NBLK * DG_];   // inclusive prefixes (4 MB)
__device__ int    g_flag[NBLK];                 // 0=none, 1=agg, 2=inclusive

__global__ void init_flags_kernel()
{
    g_flag[blockIdx.x * THREADS + threadIdx.x] = 0;
}

// ---------------------------------------------------------------------------
// Warp-specialized decoupled-lookback scan (fastest measured body, R6).
//   bid = c*NCHAIN + chain (waves span all chains -> shallow lookback).
//   Phase 1 (concurrent): h1 loads tile + 64-step scan (snapshots at 16/32/48)
//     + publishes aggregate; h0 does lookback -> carry.
//   Phase 2 (concurrent): h0 publishes inclusive; h1 builds quarter-entries.
//   Phase 3 (all 256): 4 t-quarters x 64 lanes x 2 d-lanes, float4 stores.
// ---------------------------------------------------------------------------
__global__ void __launch_bounds__(THREADS, 6) scan_kernel(
    const float* __restrict__ x,
    const float* __restrict__ Ar,
    const float* __restrict__ Ai,
    float2* __restrict__ out)
{
    __shared__ float  sx[L_ * DG_];      // 32 KB x tile, [t][d]
    __shared__ float2 sqin[4][DG_];      // quarter-entry states (sqin[0]=carry)
    __shared__ float2 sagg[DG_];         // block aggregate (h1 -> h0)

    const int tid   = threadIdx.x;
    const int bid   = blockIdx.x;
    const int chain = bid & (NCHAIN - 1);
    const int c     = bid >> 6;                 // / NCHAIN
    const int dg    = chain & (NDG - 1);
    const int b     = chain >> 2;               // / NDG
    const int h     = tid >> 7;                 // 0: lookback, 1: scan

    if (h == 1) {
        // ===== h1: tile load + 64-step scan with snapshots + agg publish =====
        const int d = tid - 128;
        const float ar = Ar[dg * DG_ + d];
        const float ai = Ai[dg * DG_ + d];

        const float* xb = x + ((size_t)b * T_ + (size_t)c * L_) * D_ + dg * DG_;
        {
            const int lane4 = d & 31;           // float4 column (32 per row)
            const int rsub  = d >> 5;           // 0..3
            float4* s4 = (float4*)sx;
            #pragma unroll
            for (int r = 0; r < L_ / 4; ++r) {
                const int row = r * 4 + rsub;
                s4[row * (DG_ / 4) + lane4] =
                    __ldcs((const float4*)(xb + (size_t)row * D_) + lane4);
            }
        }
        asm volatile("bar.sync 1, 128;" ::: "memory");   // tile ready (h1)

        const float* sxd = sx + d;
        float er = 0.0f, ei = 0.0f;
        float s16r, s16i, s32r, s32i, s48r, s48i;
        #pragma unroll
        for (int t = 0; t < L_; ++t) {
            const float xv = sxd[t * DG_];
            const float nr = fmaf(er, ar, fmaf(-ei, ai, xv));
            const float ni = fmaf(er, ai, ei * ar);
            er = nr; ei = ni;
            if (t == Q_ - 1)     { s16r = er; s16i = ei; }
            if (t == 2*Q_ - 1)   { s32r = er; s32i = ei; }
            if (t == 3*Q_ - 1)   { s48r = er; s48i = ei; }
        }
        sagg[d] = make_float2(er, ei);           // block aggregate (from zero)

        if (c == 0) {
            g_incl[(size_t)bid * DG_ + d] = make_float2(er, ei);
        } else if (c < C_ - 1) {
            g_agg[(size_t)bid * DG_ + d] = make_float2(er, ei);
        }
        __threadfence();
        asm volatile("bar.sync 1, 128;" ::: "memory");
        if (tid == 128 && c < C_ - 1) atomicExch(&g_flag[bid], c == 0 ? 2 : 1);

        __syncthreads();   // join: carry (sqin[0]) valid

        // ---- phase 2: quarter-entry states from carry + snapshots ----------
        const float2 cv = sqin[0][d];
        float p16r = ar, p16i = ai;
        #pragma unroll
        for (int k = 0; k < 4; ++k) {            // A^16
            const float nr = p16r * p16r - p16i * p16i;
            const float ni = 2.0f * p16r * p16i;
            p16r = nr; p16i = ni;
        }
        const float p32r = p16r * p16r - p16i * p16i;
        const float p32i = 2.0f * p16r * p16i;
        const float p48r = p32r * p16r - p32i * p16i;
        const float p48i = p32r * p16i + p32i * p16r;

        sqin[1][d] = make_float2(fmaf(p16r, cv.x, fmaf(-p16i, cv.y, s16r)),
                                 fmaf(p16i, cv.x, fmaf( p16r, cv.y, s16i)));
        sqin[2][d] = make_float2(fmaf(p32r, cv.x, fmaf(-p32i, cv.y, s32r)),
                                 fmaf(p32i, cv.x, fmaf( p32r, cv.y, s32i)));
        sqin[3][d] = make_float2(fmaf(p48r, cv.x, fmaf(-p48i, cv.y, s48r)),
                                 fmaf(p48i, cv.x, fmaf( p48r, cv.y, s48i)));
    } else {
        // ===== h0: lookback concurrent with h1's scan ========================
        const int d = tid;
        const float ar = Ar[dg * DG_ + d];
        const float ai = Ai[dg * DG_ + d];
        float p64r = ar, p64i = ai;
        #pragma unroll
        for (int k = 0; k < 6; ++k) {            // A^64
            const float nr = p64r * p64r - p64i * p64i;
            const float ni = 2.0f * p64r * p64i;
            p64r = nr; p64i = ni;
        }

        float cr = 0.0f, ci = 0.0f;
        if (c > 0) {
            float mr = 1.0f, mi = 0.0f;          // running multiplier A^(64k)
            int j = bid - NCHAIN;                // predecessor, same chain
            while (true) {
                volatile int* f = &g_flag[j];
                int v = *f;
                while (v == 0) { __nanosleep(40); v = *f; }
                __threadfence();                 // acquire
                const float2 val = (v == 2)
                    ? __ldcg(&g_incl[(size_t)j * DG_ + d])
                    : __ldcg(&g_agg [(size_t)j * DG_ + d]);
                cr = fmaf(mr, val.x, fmaf(-mi, val.y, cr));
                ci = fmaf(mi, val.x, fmaf( mr, val.y, ci));
                if (v == 2) break;               // prefix complete
                const float nmr = mr * p64r - mi * p64i;
                const float nmi = mr * p64i + mi * p64r;
                mr = nmr; mi = nmi;
                j -= NCHAIN;
            }
        }
        sqin[0][d] = make_float2(cr, ci);

        __syncthreads();   // join: sagg valid

        // ---- phase 2: publish inclusive = A^64*carry + agg ------------------
        if (c > 0 && c < C_ - 1) {
            const float2 ag = sagg[d];
            const float inr = fmaf(p64r, cr, fmaf(-p64i, ci, ag.x));
            const float ini = fmaf(p64i, cr, fmaf( p64r, ci, ag.y));
            g_incl[(size_t)bid * DG_ + d] = make_float2(inr, ini);
            __threadfence();
            asm volatile("bar.sync 2, 128;" ::: "memory");
            if (tid == 0) atomicExch(&g_flag[bid], 2);
        }
    }

    __syncthreads();   // sqin[0..3] valid for everyone

    // ===== phase 3: 4 quarters x 64 lanes x 2 d-lanes, float4 stores =========
    {
        const int q    = tid >> 6;               // 0..3
        const int lane = tid & 63;
        const int d0   = 2 * lane;
        const int dglb = dg * DG_ + d0;

        const float ar0 = Ar[dglb],     ai0 = Ai[dglb];
        const float ar1 = Ar[dglb + 1], ai1 = Ai[dglb + 1];

        const float4 e = ((const float4*)sqin[q])[lane];   // (r0,i0,r1,i1)
        float r0 = e.x, i0 = e.y, r1 = e.z, i1 = e.w;

        const float2* sx2 = (const float2*)sx + (size_t)q * Q_ * (DG_ / 2) + lane;
        float4* ob = (float4*)(out + ((size_t)b * T_ + (size_t)c * L_ + q * Q_) * D_ + dglb);

        #pragma unroll
        for (int t = 0; t < Q_; ++t) {
            const float2 xv = sx2[t * (DG_ / 2)];
            const float nr0 = fmaf(r0, ar0, fmaf(-i0, ai0, xv.x));
            const float ni0 = fmaf(r0, ai0, i0 * ar0);
            const float nr1 = fmaf(r1, ar1, fmaf(-i1, ai1, xv.y));
            const float ni1 = fmaf(r1, ai1, i1 * ar1);
            r0 = nr0; i0 = ni0; r1 = nr1; i1 = ni1;
            __stcs(&ob[(size_t)t * (D_ / 2)], make_float4(nr0, ni0, nr1, ni1));
        }
    }
}

// ---------------------------------------------------------------------------
// Inputs (metadata order): x [B*T*D] f32, A_real [D] f32, A_imag [D] f32.
// Output: [B, T, D, 2] f32.
// ---------------------------------------------------------------------------
extern "C" void kernel_launch(void* const* d_in, const int* in_sizes, int n_in,
                              void* d_out, int out_size)
{
    const float* x  = (const float*)d_in[0];
    const float* Ar = (const float*)d_in[1];
    const float* Ai = (const float*)d_in[2];
    float2* out = (float2*)d_out;

    init_flags_kernel<<<NBLK / THREADS, THREADS>>>();
    scan_kernel<<<NBLK, THREADS>>>(x, Ar, Ai, out);
}